// round 12
// baseline (speedup 1.0000x reference)
#include <cuda_runtime.h>
#include <math.h>

#define CAP_EPS 1e-8f

// ---------------- packed f32x2 helpers (sm_100+) ---------------------------
__device__ __forceinline__ unsigned long long pk2(float a, float b) {
    unsigned long long r;
    asm("mov.b64 %0, {%1, %2};" : "=l"(r) : "f"(a), "f"(b));
    return r;
}
__device__ __forceinline__ void fma2(unsigned long long& d,
                                     unsigned long long a, unsigned long long b) {
    asm("fma.rn.f32x2 %0, %1, %2, %0;" : "+l"(d) : "l"(a), "l"(b));
}
__device__ __forceinline__ void up2(unsigned long long v, float& a, float& b) {
    asm("mov.b64 {%0, %1}, %2;" : "=f"(a), "=f"(b) : "l"(v));
}

// ---------------- scratch (device globals; no allocation allowed) ----------
__device__ float g_pool1[64*128*42*42];   // after conv1+relu+pool  [B,128,42,42]
__device__ float g_h2[64*64*38*38];       // after conv2            [B,64,38,38]
__device__ float g_h3[64*128*16*16];      // after conv3 (stride2)  [B,128,16,16]
__device__ float g_u[64*1024*32];         // squashed primary caps  [B,1024,32]
__device__ float g_uhat[64*1024*10*16];   // predictions            [B,1024,10,16]

// ---------------- K1: conv1 9x9 (1->128) + bias + relu + maxpool2 ----------
// threads (14,8): threadIdx.x -> 3 pool columns, threadIdx.y -> oc in group.
// Even/odd column split smem; the two dy-window row sets are merged into a
// single 10-row pass; FFMA2 pairs over pool columns.
struct K1Acc { unsigned long long A, B, C; };

__device__ __forceinline__ void k1_accum(K1Acc& s, const float* wk,
                                         const float* re, const float* ro,
                                         const unsigned long long* pe,
                                         const unsigned long long* po) {
    #pragma unroll
    for (int kw = 0; kw < 9; ++kw) {
        float w = wk[kw];
        unsigned long long w2 = pk2(w, w);
        int h = kw >> 1;
        if ((kw & 1) == 0) {
            fma2(s.A, pe[h], w2);
            fma2(s.B, po[h], w2);
            fma2(s.C, pk2(re[h + 2], ro[h + 2]), w2);
        } else {
            fma2(s.A, po[h], w2);
            fma2(s.B, pe[h + 1], w2);
            fma2(s.C, pk2(ro[h + 2], re[h + 3]), w2);
        }
    }
}

__global__ __launch_bounds__(112) void k1_conv1_pool(const float* __restrict__ x,
                                                     const float* __restrict__ w1,
                                                     const float* __restrict__ b1) {
    __shared__ float img[22*96];    // row = [even 0..45 | pad | odd at +48]
    __shared__ float ws[8*81];

    int band = blockIdx.x;          // 0..5
    int ocg  = blockIdx.y;          // 0..15
    int b    = blockIdx.z;          // 0..63
    int tid  = threadIdx.y * 14 + threadIdx.x;
    int py0  = band * 7;

    {
        const float* xb = x + b * (92*92) + (2*py0) * 92;
        for (int i = tid; i < 22*92; i += 112) {
            int lr = i / 92, c = i - lr * 92;
            img[lr*96 + (c & 1)*48 + (c >> 1)] = xb[lr*92 + c];
        }
        for (int i = tid; i < 8*81; i += 112)
            ws[i] = w1[ocg * (8*81) + i];
    }
    __syncthreads();

    int px0  = threadIdx.x * 3;     // pool columns px0..px0+2
    int oc_l = threadIdx.y;
    int oc   = ocg * 8 + oc_l;
    float bias = b1[oc];
    const float* woc = ws + oc_l * 81;
    unsigned long long binit = pk2(bias, bias);

    for (int prow = 0; prow < 7; ++prow) {
        K1Acc s0 = {binit, binit, binit};   // dy = 0
        K1Acc s1 = {binit, binit, binit};   // dy = 1
        #pragma unroll
        for (int lr = 0; lr < 10; ++lr) {
            int row = 2*prow + lr;
            const float* rowe = img + row*96 + px0;
            const float* rowo = rowe + 48;
            float re[7], ro[7];
            #pragma unroll
            for (int j = 0; j < 7; ++j) { re[j] = rowe[j]; ro[j] = rowo[j]; }
            unsigned long long pe[6], po[6];
            #pragma unroll
            for (int j = 0; j < 6; ++j) {
                pe[j] = pk2(re[j], re[j + 1]);
                po[j] = pk2(ro[j], ro[j + 1]);
            }
            if (lr <= 8) k1_accum(s0, woc + lr*9,       re, ro, pe, po);
            if (lr >= 1) k1_accum(s1, woc + (lr - 1)*9, re, ro, pe, po);
        }
        float a0lo, a0hi, b0lo, b0hi, c0lo, c0hi;
        float a1lo, a1hi, b1lo, b1hi, c1lo, c1hi;
        up2(s0.A, a0lo, a0hi); up2(s0.B, b0lo, b0hi); up2(s0.C, c0lo, c0hi);
        up2(s1.A, a1lo, a1hi); up2(s1.B, b1lo, b1hi); up2(s1.C, c1lo, c1hi);
        float m0 = fmaxf(fmaxf(a0lo, b0lo), fmaxf(a1lo, b1lo));
        float m1 = fmaxf(fmaxf(a0hi, b0hi), fmaxf(a1hi, b1hi));
        float m2 = fmaxf(fmaxf(c0lo, c0hi), fmaxf(c1lo, c1hi));
        int py = py0 + prow;
        float* outp = g_pool1 + ((b*128 + oc)*42 + py)*42 + px0;
        outp[0] = fmaxf(m0, 0.0f);
        outp[1] = fmaxf(m1, 0.0f);
        outp[2] = fmaxf(m2, 0.0f);
    }
}

// ---------------- K2: conv2 5x5 (128->64), FFMA2 over oc pairs -------------
__global__ __launch_bounds__(256) void k2_conv2(const float* __restrict__ w2,
                                                const float* __restrict__ b2) {
    __shared__ float in_s[42*42];
    __shared__ float w_s[25*8];     // [j][o] so oc pairs are contiguous

    int ocg = blockIdx.x;           // 0..7
    int b   = blockIdx.y;           // 0..63
    int tid = threadIdx.x;
    int oc0 = ocg * 8;

    int pix[6], poff[6];
    #pragma unroll
    for (int p = 0; p < 6; ++p) {
        int q = tid + p * 256;
        pix[p] = q;
        if (q > 1443) q = 1443;
        int py = q / 38, px = q - py * 38;
        poff[p] = py * 42 + px;
    }

    unsigned long long acc2[4][6];
    #pragma unroll
    for (int o = 0; o < 4; ++o) {
        unsigned long long bb = pk2(b2[oc0 + 2*o], b2[oc0 + 2*o + 1]);
        #pragma unroll
        for (int p = 0; p < 6; ++p) acc2[o][p] = bb;
    }

    const float* inb = g_pool1 + b * (128*42*42);
    for (int ic = 0; ic < 128; ++ic) {
        __syncthreads();
        const float* plane = inb + ic * 1764;
        for (int i = tid; i < 1764; i += 256) in_s[i] = plane[i];
        if (tid < 200) {
            int o = tid & 7, j = tid >> 3;
            w_s[tid] = w2[(oc0 + o)*3200 + ic*25 + j];
        }
        __syncthreads();

        #pragma unroll
        for (int kh = 0; kh < 5; ++kh) {
            #pragma unroll
            for (int kw = 0; kw < 5; ++kw) {
                int j = kh*5 + kw;
                const unsigned long long* wp =
                    (const unsigned long long*)(w_s + j*8);
                unsigned long long w0 = wp[0], w1 = wp[1], w2p = wp[2], w3 = wp[3];
                #pragma unroll
                for (int p = 0; p < 6; ++p) {
                    float v = in_s[poff[p] + kh*42 + kw];
                    unsigned long long v2 = pk2(v, v);
                    fma2(acc2[0][p], v2, w0);
                    fma2(acc2[1][p], v2, w1);
                    fma2(acc2[2][p], v2, w2p);
                    fma2(acc2[3][p], v2, w3);
                }
            }
        }
    }

    #pragma unroll
    for (int o = 0; o < 4; ++o) {
        float* o0 = g_h2 + (b*64 + oc0 + 2*o) * 1444;
        float* o1 = o0 + 1444;
        #pragma unroll
        for (int p = 0; p < 6; ++p) {
            float lo, hi;
            up2(acc2[o][p], lo, hi);
            if (pix[p] < 1444) { o0[pix[p]] = lo; o1[pix[p]] = hi; }
        }
    }
}

// ---------------- K3: conv3 8x8 stride2 (64->128), FFMA2 oc pairs ----------
__global__ __launch_bounds__(128) void k3_conv3(const float* __restrict__ wc,
                                                const float* __restrict__ bc) {
    __shared__ float in_s[38*40];   // row = [even 0..18 | odd at +20]
    __shared__ float w_s[64*16];    // [t][o] so oc pairs are contiguous

    int ocg = blockIdx.x;           // 0..7
    int b   = blockIdx.y;           // 0..63
    int tid = threadIdx.x;          // 0..127
    int oc0 = ocg * 16;

    int roff[2], pixo[2];
    #pragma unroll
    for (int p = 0; p < 2; ++p) {
        int q  = tid + p * 128;     // pixel 0..255
        int py = q >> 4, px = q & 15;
        roff[p] = (2*py) * 40 + px;
        pixo[p] = q;
    }

    unsigned long long acc2[8][2];
    #pragma unroll
    for (int o = 0; o < 8; ++o) {
        unsigned long long bb = pk2(bc[oc0 + 2*o], bc[oc0 + 2*o + 1]);
        acc2[o][0] = bb; acc2[o][1] = bb;
    }

    const float* inb = g_h2 + b * (64*38*38);
    for (int ic = 0; ic < 64; ++ic) {
        __syncthreads();
        const float* plane = inb + ic * 1444;
        for (int i = tid; i < 1444; i += 128) {
            int r = i / 38, c = i - r * 38;
            in_s[r*40 + (c & 1)*20 + (c >> 1)] = plane[i];
        }
        #pragma unroll
        for (int k = 0; k < 8; ++k) {
            int idx = tid + k*128;          // 0..1023
            int o = idx & 15, t = idx >> 4;
            w_s[idx] = wc[(oc0 + o)*4096 + ic*64 + t];
        }
        __syncthreads();

        #pragma unroll
        for (int kh = 0; kh < 8; ++kh) {
            #pragma unroll
            for (int kw = 0; kw < 8; ++kw) {
                int t = kh*8 + kw;
                int base = (kw & 1)*20 + (kw >> 1) + kh*40;
                const unsigned long long* wp =
                    (const unsigned long long*)(w_s + t*16);
                unsigned long long wq[8];
                #pragma unroll
                for (int o = 0; o < 8; ++o) wq[o] = wp[o];
                #pragma unroll
                for (int p = 0; p < 2; ++p) {
                    float v = in_s[roff[p] + base];
                    unsigned long long v2 = pk2(v, v);
                    #pragma unroll
                    for (int o = 0; o < 8; ++o)
                        fma2(acc2[o][p], v2, wq[o]);
                }
            }
        }
    }

    #pragma unroll
    for (int o = 0; o < 8; ++o) {
        float* o0 = g_h3 + (b*128 + oc0 + 2*o) * 256;
        float* o1 = o0 + 256;
        #pragma unroll
        for (int p = 0; p < 2; ++p) {
            float lo, hi;
            up2(acc2[o][p], lo, hi);
            o0[pixo[p]] = lo;
            o1[pixo[p]] = hi;
        }
    }
}

// ---------------- K4: reshape/transpose + squash over 32-dim ---------------
__global__ void k4_squash_u() {
    int gid  = blockIdx.x * blockDim.x + threadIdx.x;
    int lane = gid & 31;             // vector dim i
    int gw   = gid >> 5;             // warp -> (b,p)
    int b    = gw >> 10;
    int p    = gw & 1023;
    int ct   = p >> 8;
    int rem  = p & 255;
    int yy   = rem >> 4;
    int xx   = rem & 15;
    float val = g_h3[((b * 128 + ct * 32 + lane) * 16 + yy) * 16 + xx];
    float n2 = val * val;
    #pragma unroll
    for (int s = 16; s > 0; s >>= 1) n2 += __shfl_xor_sync(0xffffffffu, n2, s);
    float scale = (n2 / (1.0f + n2)) * rsqrtf(n2 + CAP_EPS);
    g_u[(b * 1024 + p) * 32 + lane] = val * scale;
}

// ---------------- K5: u_hat[b,p,t,o] = sum_i u[b,p,i] * Wr[p,t,o,i] --------
__global__ __launch_bounds__(160) void k5_uhat(const float* __restrict__ Wr) {
    int p = blockIdx.x;
    __shared__ float wt[5120];   // transposed: wt[i*160 + (t*16+o)]
    __shared__ float us[32];
    for (int j = threadIdx.x; j < 5120; j += 160) {
        float v = Wr[p * 5120 + j];            // j = (t*16+o)*32 + i
        wt[(j & 31) * 160 + (j >> 5)] = v;     // conflict-free reads later
    }
    int tid = threadIdx.x;                     // = t*16+o
    for (int b = 0; b < 64; ++b) {
        __syncthreads();
        if (tid < 32) us[tid] = g_u[(b * 1024 + p) * 32 + tid];
        __syncthreads();
        float acc = 0.0f;
        #pragma unroll
        for (int i = 0; i < 32; ++i)
            acc = fmaf(us[i], wt[i * 160 + tid], acc);
        g_uhat[(b * 1024 + p) * 160 + tid] = acc;
    }
}

// ---------------- K6: dynamic routing (3 iters) + likelihood ---------------
__global__ __launch_bounds__(160) void k6_routing(float* __restrict__ out) {
    __shared__ float blog[10240];   // b_log[p][t]
    __shared__ float ctile[640];    // softmax coeffs for a 64-p chunk
    __shared__ float sv[160];
    __shared__ float vv[160];

    int b   = blockIdx.x;
    int tid = threadIdx.x;          // = t*16 + o
    int t   = tid >> 4;
    int o   = tid & 15;

    for (int i = tid; i < 10240; i += 160) blog[i] = 0.0f;
    __syncthreads();

    const float* uh = g_uhat + b * (1024 * 160);

    for (int iter = 0; iter < 3; ++iter) {
        float s = 0.0f;
        for (int p0 = 0; p0 < 1024; p0 += 64) {
            if (tid < 64) {
                int p = p0 + tid;
                float bl[10];
                float mx = -1e30f;
                #pragma unroll
                for (int k = 0; k < 10; ++k) { bl[k] = blog[p * 10 + k]; mx = fmaxf(mx, bl[k]); }
                float z = 0.0f;
                #pragma unroll
                for (int k = 0; k < 10; ++k) { bl[k] = expf(bl[k] - mx); z += bl[k]; }
                float inv = 1.0f / z;
                #pragma unroll
                for (int k = 0; k < 10; ++k) ctile[tid * 10 + k] = bl[k] * inv;
            }
            __syncthreads();
            #pragma unroll 4
            for (int pp = 0; pp < 64; ++pp)
                s = fmaf(ctile[pp * 10 + t], uh[(p0 + pp) * 160 + tid], s);
            __syncthreads();
        }
        sv[tid] = s;
        __syncthreads();

        float n2 = 0.0f;
        #pragma unroll
        for (int k = 0; k < 16; ++k) { float q = sv[t * 16 + k]; n2 = fmaf(q, q, n2); }
        float vval = s * (n2 / (1.0f + n2)) * rsqrtf(n2 + CAP_EPS);
        vv[tid] = vval;
        __syncthreads();

        if (iter < 2) {
            int tt = tid % 10;       // 0..9
            int pg = tid / 10;       // 0..15
            float4 v0 = *(float4*)&vv[tt * 16 + 0];
            float4 v1 = *(float4*)&vv[tt * 16 + 4];
            float4 v2 = *(float4*)&vv[tt * 16 + 8];
            float4 v3 = *(float4*)&vv[tt * 16 + 12];
            for (int k = 0; k < 64; ++k) {
                int p = pg * 64 + k;
                const float4* u4 = (const float4*)(uh + p * 160 + tt * 16);
                float4 a = u4[0], bb = u4[1], cc = u4[2], dd = u4[3];
                float d = a.x * v0.x + a.y * v0.y + a.z * v0.z + a.w * v0.w
                        + bb.x * v1.x + bb.y * v1.y + bb.z * v1.z + bb.w * v1.w
                        + cc.x * v2.x + cc.y * v2.y + cc.z * v2.z + cc.w * v2.w
                        + dd.x * v3.x + dd.y * v3.y + dd.z * v3.z + dd.w * v3.w;
                blog[p * 10 + tt] += d;
            }
            __syncthreads();
        }
    }

    if (o == 0) {
        float n2 = 0.0f;
        #pragma unroll
        for (int k = 0; k < 16; ++k) { float q = vv[t * 16 + k]; n2 = fmaf(q, q, n2); }
        out[b * 10 + t] = sqrtf(n2 + CAP_EPS);
    }
}

// ---------------- launch ---------------------------------------------------
extern "C" void kernel_launch(void* const* d_in, const int* in_sizes, int n_in,
                              void* d_out, int out_size) {
    const float* x  = (const float*)d_in[0];
    const float* w1 = (const float*)d_in[1];
    const float* b1 = (const float*)d_in[2];
    const float* w2 = (const float*)d_in[3];
    const float* b2 = (const float*)d_in[4];
    const float* wc = (const float*)d_in[5];
    const float* bc = (const float*)d_in[6];
    const float* Wr = (const float*)d_in[7];
    float* out = (float*)d_out;

    k1_conv1_pool<<<dim3(6, 16, 64), dim3(14, 8)>>>(x, w1, b1);
    k2_conv2<<<dim3(8, 64), 256>>>(w2, b2);
    k3_conv3<<<dim3(8, 64), 128>>>(wc, bc);
    k4_squash_u<<<8192, 256>>>();
    k5_uhat<<<1024, 160>>>(Wr);
    k6_routing<<<64, 160>>>(out);
}

// round 13
// speedup vs baseline: 1.0018x; 1.0018x over previous
#include <cuda_runtime.h>
#include <math.h>

#define CAP_EPS 1e-8f

// ---------------- packed f32x2 helpers (sm_100+) ---------------------------
__device__ __forceinline__ unsigned long long pk2(float a, float b) {
    unsigned long long r;
    asm("mov.b64 %0, {%1, %2};" : "=l"(r) : "f"(a), "f"(b));
    return r;
}
__device__ __forceinline__ void fma2(unsigned long long& d,
                                     unsigned long long a, unsigned long long b) {
    asm("fma.rn.f32x2 %0, %1, %2, %0;" : "+l"(d) : "l"(a), "l"(b));
}
__device__ __forceinline__ void up2(unsigned long long v, float& a, float& b) {
    asm("mov.b64 {%0, %1}, %2;" : "=f"(a), "=f"(b) : "l"(v));
}

// ---------------- scratch (device globals; no allocation allowed) ----------
__device__ float g_pool1[64*128*42*42];   // after conv1+relu+pool  [B,128,42,42]
__device__ float g_h2[64*64*38*38];       // after conv2            [B,64,38,38]
__device__ float g_h3[64*128*16*16];      // after conv3 (stride2)  [B,128,16,16]
__device__ float g_u[64*1024*32];         // squashed primary caps  [B,1024,32]
__device__ float g_uhat[64*1024*10*16];   // predictions            [B,1024,10,16]

// ---------------- K1: conv1 9x9 (1->128) + bias + relu + maxpool2 ----------
// threads (14,8): threadIdx.x -> 3 pool columns, threadIdx.y -> oc in group.
// Even/odd column split smem; the two dy-window row sets are merged into a
// single 10-row pass; FFMA2 pairs over pool columns.
struct K1Acc { unsigned long long A, B, C; };

__device__ __forceinline__ void k1_accum(K1Acc& s, const float* wk,
                                         const float* re, const float* ro,
                                         const unsigned long long* pe,
                                         const unsigned long long* po) {
    #pragma unroll
    for (int kw = 0; kw < 9; ++kw) {
        float w = wk[kw];
        unsigned long long w2 = pk2(w, w);
        int h = kw >> 1;
        if ((kw & 1) == 0) {
            fma2(s.A, pe[h], w2);
            fma2(s.B, po[h], w2);
            fma2(s.C, pk2(re[h + 2], ro[h + 2]), w2);
        } else {
            fma2(s.A, po[h], w2);
            fma2(s.B, pe[h + 1], w2);
            fma2(s.C, pk2(ro[h + 2], re[h + 3]), w2);
        }
    }
}

__global__ __launch_bounds__(112) void k1_conv1_pool(const float* __restrict__ x,
                                                     const float* __restrict__ w1,
                                                     const float* __restrict__ b1) {
    __shared__ float img[22*96];    // row = [even 0..45 | pad | odd at +48]
    __shared__ float ws[8*81];

    int band = blockIdx.x;          // 0..5
    int ocg  = blockIdx.y;          // 0..15
    int b    = blockIdx.z;          // 0..63
    int tid  = threadIdx.y * 14 + threadIdx.x;
    int py0  = band * 7;

    {
        const float* xb = x + b * (92*92) + (2*py0) * 92;
        for (int i = tid; i < 22*92; i += 112) {
            int lr = i / 92, c = i - lr * 92;
            img[lr*96 + (c & 1)*48 + (c >> 1)] = xb[lr*92 + c];
        }
        for (int i = tid; i < 8*81; i += 112)
            ws[i] = w1[ocg * (8*81) + i];
    }
    __syncthreads();

    int px0  = threadIdx.x * 3;     // pool columns px0..px0+2
    int oc_l = threadIdx.y;
    int oc   = ocg * 8 + oc_l;
    float bias = b1[oc];
    const float* woc = ws + oc_l * 81;
    unsigned long long binit = pk2(bias, bias);

    for (int prow = 0; prow < 7; ++prow) {
        K1Acc s0 = {binit, binit, binit};   // dy = 0
        K1Acc s1 = {binit, binit, binit};   // dy = 1
        #pragma unroll
        for (int lr = 0; lr < 10; ++lr) {
            int row = 2*prow + lr;
            const float* rowe = img + row*96 + px0;
            const float* rowo = rowe + 48;
            float re[7], ro[7];
            #pragma unroll
            for (int j = 0; j < 7; ++j) { re[j] = rowe[j]; ro[j] = rowo[j]; }
            unsigned long long pe[6], po[6];
            #pragma unroll
            for (int j = 0; j < 6; ++j) {
                pe[j] = pk2(re[j], re[j + 1]);
                po[j] = pk2(ro[j], ro[j + 1]);
            }
            if (lr <= 8) k1_accum(s0, woc + lr*9,       re, ro, pe, po);
            if (lr >= 1) k1_accum(s1, woc + (lr - 1)*9, re, ro, pe, po);
        }
        float a0lo, a0hi, b0lo, b0hi, c0lo, c0hi;
        float a1lo, a1hi, b1lo, b1hi, c1lo, c1hi;
        up2(s0.A, a0lo, a0hi); up2(s0.B, b0lo, b0hi); up2(s0.C, c0lo, c0hi);
        up2(s1.A, a1lo, a1hi); up2(s1.B, b1lo, b1hi); up2(s1.C, c1lo, c1hi);
        float m0 = fmaxf(fmaxf(a0lo, b0lo), fmaxf(a1lo, b1lo));
        float m1 = fmaxf(fmaxf(a0hi, b0hi), fmaxf(a1hi, b1hi));
        float m2 = fmaxf(fmaxf(c0lo, c0hi), fmaxf(c1lo, c1hi));
        int py = py0 + prow;
        float* outp = g_pool1 + ((b*128 + oc)*42 + py)*42 + px0;
        outp[0] = fmaxf(m0, 0.0f);
        outp[1] = fmaxf(m1, 0.0f);
        outp[2] = fmaxf(m2, 0.0f);
    }
}

// ---------------- K2: conv2 5x5 (128->64), FFMA2 over oc pairs -------------
__global__ __launch_bounds__(256) void k2_conv2(const float* __restrict__ w2,
                                                const float* __restrict__ b2) {
    __shared__ float in_s[42*42];
    __shared__ float w_s[25*8];     // [j][o] so oc pairs are contiguous

    int ocg = blockIdx.x;           // 0..7
    int b   = blockIdx.y;           // 0..63
    int tid = threadIdx.x;
    int oc0 = ocg * 8;

    int pix[6], poff[6];
    #pragma unroll
    for (int p = 0; p < 6; ++p) {
        int q = tid + p * 256;
        pix[p] = q;
        if (q > 1443) q = 1443;
        int py = q / 38, px = q - py * 38;
        poff[p] = py * 42 + px;
    }

    unsigned long long acc2[4][6];
    #pragma unroll
    for (int o = 0; o < 4; ++o) {
        unsigned long long bb = pk2(b2[oc0 + 2*o], b2[oc0 + 2*o + 1]);
        #pragma unroll
        for (int p = 0; p < 6; ++p) acc2[o][p] = bb;
    }

    const float* inb = g_pool1 + b * (128*42*42);
    for (int ic = 0; ic < 128; ++ic) {
        __syncthreads();
        const float* plane = inb + ic * 1764;
        for (int i = tid; i < 1764; i += 256) in_s[i] = plane[i];
        if (tid < 200) {
            int o = tid & 7, j = tid >> 3;
            w_s[tid] = w2[(oc0 + o)*3200 + ic*25 + j];
        }
        __syncthreads();

        #pragma unroll
        for (int kh = 0; kh < 5; ++kh) {
            #pragma unroll
            for (int kw = 0; kw < 5; ++kw) {
                int j = kh*5 + kw;
                const unsigned long long* wp =
                    (const unsigned long long*)(w_s + j*8);
                unsigned long long w0 = wp[0], w1 = wp[1], w2p = wp[2], w3 = wp[3];
                #pragma unroll
                for (int p = 0; p < 6; ++p) {
                    float v = in_s[poff[p] + kh*42 + kw];
                    unsigned long long v2 = pk2(v, v);
                    fma2(acc2[0][p], v2, w0);
                    fma2(acc2[1][p], v2, w1);
                    fma2(acc2[2][p], v2, w2p);
                    fma2(acc2[3][p], v2, w3);
                }
            }
        }
    }

    #pragma unroll
    for (int o = 0; o < 4; ++o) {
        float* o0 = g_h2 + (b*64 + oc0 + 2*o) * 1444;
        float* o1 = o0 + 1444;
        #pragma unroll
        for (int p = 0; p < 6; ++p) {
            float lo, hi;
            up2(acc2[o][p], lo, hi);
            if (pix[p] < 1444) { o0[pix[p]] = lo; o1[pix[p]] = hi; }
        }
    }
}

// ---------------- K3: conv3 8x8 stride2 (64->128), FFMA2 oc pairs ----------
__global__ __launch_bounds__(128) void k3_conv3(const float* __restrict__ wc,
                                                const float* __restrict__ bc) {
    __shared__ float in_s[38*40];   // row = [even 0..18 | odd at +20]
    __shared__ float w_s[64*16];    // [t][o] so oc pairs are contiguous

    int ocg = blockIdx.x;           // 0..7
    int b   = blockIdx.y;           // 0..63
    int tid = threadIdx.x;          // 0..127
    int oc0 = ocg * 16;

    int roff[2], pixo[2];
    #pragma unroll
    for (int p = 0; p < 2; ++p) {
        int q  = tid + p * 128;     // pixel 0..255
        int py = q >> 4, px = q & 15;
        roff[p] = (2*py) * 40 + px;
        pixo[p] = q;
    }

    unsigned long long acc2[8][2];
    #pragma unroll
    for (int o = 0; o < 8; ++o) {
        unsigned long long bb = pk2(bc[oc0 + 2*o], bc[oc0 + 2*o + 1]);
        acc2[o][0] = bb; acc2[o][1] = bb;
    }

    const float* inb = g_h2 + b * (64*38*38);
    for (int ic = 0; ic < 64; ++ic) {
        __syncthreads();
        const float* plane = inb + ic * 1444;
        for (int i = tid; i < 1444; i += 128) {
            int r = i / 38, c = i - r * 38;
            in_s[r*40 + (c & 1)*20 + (c >> 1)] = plane[i];
        }
        #pragma unroll
        for (int k = 0; k < 8; ++k) {
            int idx = tid + k*128;          // 0..1023
            int o = idx & 15, t = idx >> 4;
            w_s[idx] = wc[(oc0 + o)*4096 + ic*64 + t];
        }
        __syncthreads();

        #pragma unroll
        for (int kh = 0; kh < 8; ++kh) {
            #pragma unroll
            for (int kw = 0; kw < 8; ++kw) {
                int t = kh*8 + kw;
                int base = (kw & 1)*20 + (kw >> 1) + kh*40;
                const unsigned long long* wp =
                    (const unsigned long long*)(w_s + t*16);
                unsigned long long wq[8];
                #pragma unroll
                for (int o = 0; o < 8; ++o) wq[o] = wp[o];
                #pragma unroll
                for (int p = 0; p < 2; ++p) {
                    float v = in_s[roff[p] + base];
                    unsigned long long v2 = pk2(v, v);
                    #pragma unroll
                    for (int o = 0; o < 8; ++o)
                        fma2(acc2[o][p], v2, wq[o]);
                }
            }
        }
    }

    #pragma unroll
    for (int o = 0; o < 8; ++o) {
        float* o0 = g_h3 + (b*128 + oc0 + 2*o) * 256;
        float* o1 = o0 + 256;
        #pragma unroll
        for (int p = 0; p < 2; ++p) {
            float lo, hi;
            up2(acc2[o][p], lo, hi);
            o0[pixo[p]] = lo;
            o1[pixo[p]] = hi;
        }
    }
}

// ---------------- K4: reshape/transpose + squash over 32-dim ---------------
__global__ void k4_squash_u() {
    int gid  = blockIdx.x * blockDim.x + threadIdx.x;
    int lane = gid & 31;             // vector dim i
    int gw   = gid >> 5;             // warp -> (b,p)
    int b    = gw >> 10;
    int p    = gw & 1023;
    int ct   = p >> 8;
    int rem  = p & 255;
    int yy   = rem >> 4;
    int xx   = rem & 15;
    float val = g_h3[((b * 128 + ct * 32 + lane) * 16 + yy) * 16 + xx];
    float n2 = val * val;
    #pragma unroll
    for (int s = 16; s > 0; s >>= 1) n2 += __shfl_xor_sync(0xffffffffu, n2, s);
    float scale = (n2 / (1.0f + n2)) * rsqrtf(n2 + CAP_EPS);
    g_u[(b * 1024 + p) * 32 + lane] = val * scale;
}

// ---------------- K5: u_hat[b,p,t,o] = sum_i u[b,p,i] * Wr[p,t,o,i] --------
__global__ __launch_bounds__(160) void k5_uhat(const float* __restrict__ Wr) {
    int p = blockIdx.x;
    __shared__ float wt[5120];   // transposed: wt[i*160 + (t*16+o)]
    __shared__ float us[32];
    for (int j = threadIdx.x; j < 5120; j += 160) {
        float v = Wr[p * 5120 + j];            // j = (t*16+o)*32 + i
        wt[(j & 31) * 160 + (j >> 5)] = v;     // conflict-free reads later
    }
    int tid = threadIdx.x;                     // = t*16+o
    for (int b = 0; b < 64; ++b) {
        __syncthreads();
        if (tid < 32) us[tid] = g_u[(b * 1024 + p) * 32 + tid];
        __syncthreads();
        float acc = 0.0f;
        #pragma unroll
        for (int i = 0; i < 32; ++i)
            acc = fmaf(us[i], wt[i * 160 + tid], acc);
        g_uhat[(b * 1024 + p) * 160 + tid] = acc;
    }
}

// ---------------- K6: dynamic routing (3 iters) + likelihood ---------------
__global__ __launch_bounds__(160) void k6_routing(float* __restrict__ out) {
    __shared__ float blog[10240];   // b_log[p][t]
    __shared__ float ctile[640];    // softmax coeffs for a 64-p chunk
    __shared__ float sv[160];
    __shared__ float vv[160];

    int b   = blockIdx.x;
    int tid = threadIdx.x;          // = t*16 + o
    int t   = tid >> 4;
    int o   = tid & 15;

    for (int i = tid; i < 10240; i += 160) blog[i] = 0.0f;
    __syncthreads();

    const float* uh = g_uhat + b * (1024 * 160);

    for (int iter = 0; iter < 3; ++iter) {
        float s = 0.0f;
        for (int p0 = 0; p0 < 1024; p0 += 64) {
            if (tid < 64) {
                int p = p0 + tid;
                float bl[10];
                float mx = -1e30f;
                #pragma unroll
                for (int k = 0; k < 10; ++k) { bl[k] = blog[p * 10 + k]; mx = fmaxf(mx, bl[k]); }
                float z = 0.0f;
                #pragma unroll
                for (int k = 0; k < 10; ++k) { bl[k] = expf(bl[k] - mx); z += bl[k]; }
                float inv = 1.0f / z;
                #pragma unroll
                for (int k = 0; k < 10; ++k) ctile[tid * 10 + k] = bl[k] * inv;
            }
            __syncthreads();
            #pragma unroll 4
            for (int pp = 0; pp < 64; ++pp)
                s = fmaf(ctile[pp * 10 + t], uh[(p0 + pp) * 160 + tid], s);
            __syncthreads();
        }
        sv[tid] = s;
        __syncthreads();

        float n2 = 0.0f;
        #pragma unroll
        for (int k = 0; k < 16; ++k) { float q = sv[t * 16 + k]; n2 = fmaf(q, q, n2); }
        float vval = s * (n2 / (1.0f + n2)) * rsqrtf(n2 + CAP_EPS);
        vv[tid] = vval;
        __syncthreads();

        if (iter < 2) {
            int tt = tid % 10;       // 0..9
            int pg = tid / 10;       // 0..15
            float4 v0 = *(float4*)&vv[tt * 16 + 0];
            float4 v1 = *(float4*)&vv[tt * 16 + 4];
            float4 v2 = *(float4*)&vv[tt * 16 + 8];
            float4 v3 = *(float4*)&vv[tt * 16 + 12];
            for (int k = 0; k < 64; ++k) {
                int p = pg * 64 + k;
                const float4* u4 = (const float4*)(uh + p * 160 + tt * 16);
                float4 a = u4[0], bb = u4[1], cc = u4[2], dd = u4[3];
                float d = a.x * v0.x + a.y * v0.y + a.z * v0.z + a.w * v0.w
                        + bb.x * v1.x + bb.y * v1.y + bb.z * v1.z + bb.w * v1.w
                        + cc.x * v2.x + cc.y * v2.y + cc.z * v2.z + cc.w * v2.w
                        + dd.x * v3.x + dd.y * v3.y + dd.z * v3.z + dd.w * v3.w;
                blog[p * 10 + tt] += d;
            }
            __syncthreads();
        }
    }

    if (o == 0) {
        float n2 = 0.0f;
        #pragma unroll
        for (int k = 0; k < 16; ++k) { float q = vv[t * 16 + k]; n2 = fmaf(q, q, n2); }
        out[b * 10 + t] = sqrtf(n2 + CAP_EPS);
    }
}

// ---------------- launch ---------------------------------------------------
extern "C" void kernel_launch(void* const* d_in, const int* in_sizes, int n_in,
                              void* d_out, int out_size) {
    const float* x  = (const float*)d_in[0];
    const float* w1 = (const float*)d_in[1];
    const float* b1 = (const float*)d_in[2];
    const float* w2 = (const float*)d_in[3];
    const float* b2 = (const float*)d_in[4];
    const float* wc = (const float*)d_in[5];
    const float* bc = (const float*)d_in[6];
    const float* Wr = (const float*)d_in[7];
    float* out = (float*)d_out;

    k1_conv1_pool<<<dim3(6, 16, 64), dim3(14, 8)>>>(x, w1, b1);
    k2_conv2<<<dim3(8, 64), 256>>>(w2, b2);
    k3_conv3<<<dim3(8, 64), 128>>>(wc, bc);
    k4_squash_u<<<8192, 256>>>();
    k5_uhat<<<1024, 160>>>(Wr);
    k6_routing<<<64, 160>>>(out);
}

// round 15
// speedup vs baseline: 1.3754x; 1.3729x over previous
#include <cuda_runtime.h>
#include <cuda_bf16.h>
#include <math.h>
#include <stdint.h>

#define CAP_EPS 1e-8f

// ---------------- packed f32x2 helpers (sm_100+) ---------------------------
__device__ __forceinline__ unsigned long long pk2(float a, float b) {
    unsigned long long r;
    asm("mov.b64 %0, {%1, %2};" : "=l"(r) : "f"(a), "f"(b));
    return r;
}
__device__ __forceinline__ void fma2(unsigned long long& d,
                                     unsigned long long a, unsigned long long b) {
    asm("fma.rn.f32x2 %0, %1, %2, %0;" : "+l"(d) : "l"(a), "l"(b));
}
__device__ __forceinline__ void up2(unsigned long long v, float& a, float& b) {
    asm("mov.b64 {%0, %1}, %2;" : "=f"(a), "=f"(b) : "l"(v));
}

// ---------------- warp-MMA helpers (generic PTX, sm_80+) -------------------
__device__ __forceinline__ uint32_t smem_u32(const void* p) {
    return (uint32_t)__cvta_generic_to_shared(p);
}
__device__ __forceinline__ void ldsm4(uint32_t addr, uint32_t* r) {
    asm volatile("ldmatrix.sync.aligned.m8n8.x4.shared.b16 {%0,%1,%2,%3}, [%4];"
                 : "=r"(r[0]), "=r"(r[1]), "=r"(r[2]), "=r"(r[3]) : "r"(addr));
}
__device__ __forceinline__ void mma16816(float* c, const uint32_t* a,
                                         const uint32_t* b) {
    asm volatile(
        "mma.sync.aligned.m16n8k16.row.col.f32.bf16.bf16.f32 "
        "{%0,%1,%2,%3}, {%4,%5,%6,%7}, {%8,%9}, {%0,%1,%2,%3};"
        : "+f"(c[0]), "+f"(c[1]), "+f"(c[2]), "+f"(c[3])
        : "r"(a[0]), "r"(a[1]), "r"(a[2]), "r"(a[3]), "r"(b[0]), "r"(b[1]));
}

// bf16 hi/lo split packing: hi in bits[0:16), lo in bits[16:32)
__device__ __forceinline__ unsigned packsplit(float v) {
    __nv_bfloat16 h = __float2bfloat16(v);
    float hf = __bfloat162float(h);
    __nv_bfloat16 l = __float2bfloat16(v - hf);
    return (unsigned)__bfloat16_as_ushort(h)
         | ((unsigned)__bfloat16_as_ushort(l) << 16);
}

// ---------------- scratch (device globals; no allocation allowed) ----------
__device__ unsigned g_x2[64*1764*128];    // conv2 input NHWC, packed bf16 hi|lo
__device__ float g_h2[64*64*38*38];       // after conv2 (NCHW fp32)
__device__ float g_h3[64*128*16*16];      // after conv3 (stride2)  [B,128,16,16]
__device__ float g_u[64*1024*32];         // squashed primary caps  [B,1024,32]
__device__ float g_uhat[64*1024*10*16];   // predictions            [B,1024,10,16]
__device__ unsigned g_w2n[25*4*2560];     // conv2 W tiles: [tap][kc][hi|lo], pitch 40

// ---------------- K1: conv1 9x9 (1->128) + bias + relu + maxpool2 ----------
struct K1Acc { unsigned long long A, B, C; };

__device__ __forceinline__ void k1_accum(K1Acc& s, const float* wk,
                                         const float* re, const float* ro,
                                         const unsigned long long* pe,
                                         const unsigned long long* po) {
    #pragma unroll
    for (int kw = 0; kw < 9; ++kw) {
        float w = wk[kw];
        unsigned long long w2 = pk2(w, w);
        int h = kw >> 1;
        if ((kw & 1) == 0) {
            fma2(s.A, pe[h], w2);
            fma2(s.B, po[h], w2);
            fma2(s.C, pk2(re[h + 2], ro[h + 2]), w2);
        } else {
            fma2(s.A, po[h], w2);
            fma2(s.B, pe[h + 1], w2);
            fma2(s.C, pk2(ro[h + 2], re[h + 3]), w2);
        }
    }
}

__global__ __launch_bounds__(112) void k1_conv1_pool(const float* __restrict__ x,
                                                     const float* __restrict__ w1,
                                                     const float* __restrict__ b1) {
    __shared__ float img[22*96];
    __shared__ float ws[8*81];

    int band = blockIdx.x;
    int ocg  = blockIdx.y;
    int b    = blockIdx.z;
    int tid  = threadIdx.y * 14 + threadIdx.x;
    int py0  = band * 7;

    {
        const float* xb = x + b * (92*92) + (2*py0) * 92;
        for (int i = tid; i < 22*92; i += 112) {
            int lr = i / 92, c = i - lr * 92;
            img[lr*96 + (c & 1)*48 + (c >> 1)] = xb[lr*92 + c];
        }
        for (int i = tid; i < 8*81; i += 112)
            ws[i] = w1[ocg * (8*81) + i];
    }
    __syncthreads();

    int px0  = threadIdx.x * 3;
    int oc_l = threadIdx.y;
    int oc   = ocg * 8 + oc_l;
    float bias = b1[oc];
    const float* woc = ws + oc_l * 81;
    unsigned long long binit = pk2(bias, bias);

    for (int prow = 0; prow < 7; ++prow) {
        K1Acc s0 = {binit, binit, binit};
        K1Acc s1 = {binit, binit, binit};
        #pragma unroll
        for (int lr = 0; lr < 10; ++lr) {
            int row = 2*prow + lr;
            const float* rowe = img + row*96 + px0;
            const float* rowo = rowe + 48;
            float re[7], ro[7];
            #pragma unroll
            for (int j = 0; j < 7; ++j) { re[j] = rowe[j]; ro[j] = rowo[j]; }
            unsigned long long pe[6], po[6];
            #pragma unroll
            for (int j = 0; j < 6; ++j) {
                pe[j] = pk2(re[j], re[j + 1]);
                po[j] = pk2(ro[j], ro[j + 1]);
            }
            if (lr <= 8) k1_accum(s0, woc + lr*9,       re, ro, pe, po);
            if (lr >= 1) k1_accum(s1, woc + (lr - 1)*9, re, ro, pe, po);
        }
        float a0lo, a0hi, b0lo, b0hi, c0lo, c0hi;
        float a1lo, a1hi, b1lo, b1hi, c1lo, c1hi;
        up2(s0.A, a0lo, a0hi); up2(s0.B, b0lo, b0hi); up2(s0.C, c0lo, c0hi);
        up2(s1.A, a1lo, a1hi); up2(s1.B, b1lo, b1hi); up2(s1.C, c1lo, c1hi);
        float m0 = fmaxf(fmaxf(a0lo, b0lo), fmaxf(a1lo, b1lo));
        float m1 = fmaxf(fmaxf(a0hi, b0hi), fmaxf(a1hi, b1hi));
        float m2 = fmaxf(fmaxf(c0lo, c0hi), fmaxf(c1lo, c1hi));
        int py = py0 + prow;
        // NHWC packed hi|lo for k2's implicit GEMM
        unsigned* outp = g_x2 + ((size_t)b*1764 + py*42 + px0)*128 + oc;
        outp[0]   = packsplit(fmaxf(m0, 0.0f));
        outp[128] = packsplit(fmaxf(m1, 0.0f));
        outp[256] = packsplit(fmaxf(m2, 0.0f));
    }
}

// ---------------- K2w: pack conv2 weights into smem-image tiles ------------
// per (tap, kc): hi tile [64 oc rows x 32 k, pitch 40 bf16] (1280 u32),
// then lo tile (1280 u32).
__global__ void k2w_pack(const float* __restrict__ w2) {
    int i = blockIdx.x * 256 + threadIdx.x;   // 25*4*64*16 = 102400
    if (i >= 102400) return;
    int tap  = i / 4096;
    int rem  = i & 4095;
    int kc   = rem >> 10;
    int rem2 = rem & 1023;
    int oc   = rem2 >> 4;
    int cp   = rem2 & 15;
    int ic0  = kc*32 + cp*2;
    float v0 = w2[oc*3200 + ic0*25 + tap];
    float v1 = w2[oc*3200 + (ic0 + 1)*25 + tap];
    unsigned p0 = packsplit(v0), p1 = packsplit(v1);
    unsigned base = (unsigned)(tap*4 + kc)*2560;
    g_w2n[base + oc*20 + cp]        = (p0 & 0xffffu) | (p1 << 16);
    g_w2n[base + 1280 + oc*20 + cp] = (p0 >> 16) | (p1 & 0xffff0000u);
}

// ---------------- K2: conv2 5x5 (128->64) via mma.sync implicit GEMM -------
// CTA = (128-px tile, batch). M=128 px, N=64 oc, K = 25 taps x 128 ic.
// A patch (9 rows x 42 cols x 32 ic) staged per ic-chunk; taps are per-lane
// row-offset shifts. bf16 3-pass split, fp32 accumulators.
#define K2_AH   0
#define K2_AL   30240
#define K2_B0   60480
#define K2_B1   70720
#define K2_SMEM 80960

__global__ __launch_bounds__(256, 2) void k2_conv2_mma(const float* __restrict__ b2) {
    extern __shared__ char smem[];
    uint32_t sb = smem_u32(smem);
    int tid = threadIdx.x, lane = tid & 31, warp = tid >> 5;
    int tile = blockIdx.x, b = blockIdx.y;
    int px0 = tile * 128;
    int r0  = px0 / 38;

    int m0 = (warp >> 1) * 32;
    int n0 = (warp & 1) * 32;

    // per-lane ldmatrix offsets
    uint32_t aoff[2];
    #pragma unroll
    for (int f = 0; f < 2; ++f) {
        int m = m0 + f*16 + (lane & 15);
        int px = px0 + m; if (px > 1443) px = 1443;
        int y = px / 38, xx = px - y*38;
        int prow = (y - r0)*42 + xx;
        aoff[f] = (uint32_t)(prow*80 + ((lane >> 4) ? 16 : 0));
    }
    uint32_t boff[2];
    #pragma unroll
    for (int g = 0; g < 2; ++g) {
        int row = n0 + g*16 + (lane & 7) + ((lane >= 16) ? 8 : 0);
        boff[g] = (uint32_t)(row*80 + (((lane >> 3) & 1) ? 16 : 0));
    }

    float acc[2][4][4];
    #pragma unroll
    for (int mf = 0; mf < 2; ++mf)
        #pragma unroll
        for (int nf = 0; nf < 4; ++nf)
            #pragma unroll
            for (int j = 0; j < 4; ++j) acc[mf][nf][j] = 0.0f;

    unsigned* awh = (unsigned*)(smem + K2_AH);
    unsigned* awl = (unsigned*)(smem + K2_AL);
    const unsigned* xsrc = g_x2 + (size_t)b * (1764*128);

    for (int kc = 0; kc < 4; ++kc) {
        __syncthreads();
        // stage A patch: 378 pixels x 16 col-pairs
        for (int i = tid; i < 378*16; i += 256) {
            int pix = i >> 4, cp = i & 15;
            int pr = pix / 42, pc = pix - pr*42;
            int row = r0 + pr; if (row > 41) row = 41;
            const unsigned* s = xsrc + (size_t)(row*42 + pc)*128 + kc*32 + cp*2;
            unsigned p0 = s[0], p1 = s[1];
            awh[pix*20 + cp] = (p0 & 0xffffu) | (p1 << 16);
            awl[pix*20 + cp] = (p0 >> 16) | (p1 & 0xffff0000u);
        }
        // stage B for tap 0
        {
            const unsigned* wsrc = g_w2n + (unsigned)kc*2560;
            unsigned* d = (unsigned*)(smem + K2_B0);
            for (int i = tid; i < 2560; i += 256) d[i] = wsrc[i];
        }
        __syncthreads();

        for (int tap = 0; tap < 25; ++tap) {
            int buf = tap & 1;
            if (tap + 1 < 25) {     // prefetch next tap's weights
                const unsigned* wsrc = g_w2n + (unsigned)((tap + 1)*4 + kc)*2560;
                unsigned* d = (unsigned*)(smem + (buf ? K2_B0 : K2_B1));
                for (int i = tid; i < 2560; i += 256) d[i] = wsrc[i];
            }
            int kh = tap / 5, kw = tap - kh*5;
            uint32_t toff = (uint32_t)(kh*42 + kw) * 80;
            uint32_t aH0 = sb + K2_AH + aoff[0] + toff;
            uint32_t aH1 = sb + K2_AH + aoff[1] + toff;
            uint32_t aL0 = sb + K2_AL + aoff[0] + toff;
            uint32_t aL1 = sb + K2_AL + aoff[1] + toff;
            uint32_t bB  = sb + (buf ? K2_B1 : K2_B0);
            uint32_t bH0 = bB + boff[0],        bH1 = bB + boff[1];
            uint32_t bL0 = bB + 5120 + boff[0], bL1 = bB + 5120 + boff[1];

            #pragma unroll
            for (int ks = 0; ks < 2; ++ks) {
                uint32_t ah[2][4], al[2][4], bh[2][4], bl[2][4];
                ldsm4(aH0 + ks*32, ah[0]); ldsm4(aH1 + ks*32, ah[1]);
                ldsm4(aL0 + ks*32, al[0]); ldsm4(aL1 + ks*32, al[1]);
                ldsm4(bH0 + ks*32, bh[0]); ldsm4(bH1 + ks*32, bh[1]);
                ldsm4(bL0 + ks*32, bl[0]); ldsm4(bL1 + ks*32, bl[1]);
                #pragma unroll
                for (int mf = 0; mf < 2; ++mf) {
                    #pragma unroll
                    for (int nf = 0; nf < 4; ++nf) {
                        const uint32_t* bhp = &bh[nf >> 1][(nf & 1)*2];
                        const uint32_t* blp = &bl[nf >> 1][(nf & 1)*2];
                        mma16816(acc[mf][nf], ah[mf], bhp);
                        mma16816(acc[mf][nf], al[mf], bhp);
                        mma16816(acc[mf][nf], ah[mf], blp);
                    }
                }
            }
            __syncthreads();
        }
    }

    // epilogue: bias + store fp32 NCHW
    #pragma unroll
    for (int mf = 0; mf < 2; ++mf) {
        #pragma unroll
        for (int j2 = 0; j2 < 2; ++j2) {
            int px = px0 + m0 + mf*16 + (lane >> 2) + j2*8;
            if (px < 1444) {
                #pragma unroll
                for (int nf = 0; nf < 4; ++nf) {
                    int oc = n0 + nf*8 + (lane & 3)*2;
                    float v0 = acc[mf][nf][j2*2 + 0] + b2[oc];
                    float v1 = acc[mf][nf][j2*2 + 1] + b2[oc + 1];
                    g_h2[(size_t)(b*64 + oc)*1444 + px] = v0;
                    g_h2[(size_t)(b*64 + oc + 1)*1444 + px] = v1;
                }
            }
        }
    }
}

// ---------------- K3: conv3 8x8 stride2 (64->128), FFMA2 oc pairs ----------
__global__ __launch_bounds__(128) void k3_conv3(const float* __restrict__ wc,
                                                const float* __restrict__ bc) {
    __shared__ float in_s[38*40];
    __shared__ float w_s[64*16];

    int ocg = blockIdx.x;
    int b   = blockIdx.y;
    int tid = threadIdx.x;
    int oc0 = ocg * 16;

    int roff[2], pixo[2];
    #pragma unroll
    for (int p = 0; p < 2; ++p) {
        int q  = tid + p * 128;
        int py = q >> 4, px = q & 15;
        roff[p] = (2*py) * 40 + px;
        pixo[p] = q;
    }

    unsigned long long acc2[8][2];
    #pragma unroll
    for (int o = 0; o < 8; ++o) {
        unsigned long long bb = pk2(bc[oc0 + 2*o], bc[oc0 + 2*o + 1]);
        acc2[o][0] = bb; acc2[o][1] = bb;
    }

    const float* inb = g_h2 + (size_t)b * (64*38*38);
    for (int ic = 0; ic < 64; ++ic) {
        __syncthreads();
        const float* plane = inb + ic * 1444;
        for (int i = tid; i < 1444; i += 128) {
            int rr = i / 38, cc = i - rr * 38;
            in_s[rr*40 + (cc & 1)*20 + (cc >> 1)] = plane[i];
        }
        #pragma unroll
        for (int k = 0; k < 8; ++k) {
            int idx = tid + k*128;
            int o = idx & 15, t = idx >> 4;
            w_s[idx] = wc[(oc0 + o)*4096 + ic*64 + t];
        }
        __syncthreads();

        #pragma unroll
        for (int kh = 0; kh < 8; ++kh) {
            #pragma unroll
            for (int kw = 0; kw < 8; ++kw) {
                int t = kh*8 + kw;
                int base = (kw & 1)*20 + (kw >> 1) + kh*40;
                const unsigned long long* wp =
                    (const unsigned long long*)(w_s + t*16);
                unsigned long long wq[8];
                #pragma unroll
                for (int o = 0; o < 8; ++o) wq[o] = wp[o];
                #pragma unroll
                for (int p = 0; p < 2; ++p) {
                    float v = in_s[roff[p] + base];
                    unsigned long long v2 = pk2(v, v);
                    #pragma unroll
                    for (int o = 0; o < 8; ++o)
                        fma2(acc2[o][p], v2, wq[o]);
                }
            }
        }
    }

    #pragma unroll
    for (int o = 0; o < 8; ++o) {
        float* o0 = g_h3 + (b*128 + oc0 + 2*o) * 256;
        float* o1 = o0 + 256;
        #pragma unroll
        for (int p = 0; p < 2; ++p) {
            float lo, hi;
            up2(acc2[o][p], lo, hi);
            o0[pixo[p]] = lo;
            o1[pixo[p]] = hi;
        }
    }
}

// ---------------- K4: reshape/transpose + squash over 32-dim ---------------
__global__ void k4_squash_u() {
    int gid  = blockIdx.x * blockDim.x + threadIdx.x;
    int lane = gid & 31;
    int gw   = gid >> 5;
    int b    = gw >> 10;
    int p    = gw & 1023;
    int ct   = p >> 8;
    int rem  = p & 255;
    int yy   = rem >> 4;
    int xx   = rem & 15;
    float val = g_h3[((b * 128 + ct * 32 + lane) * 16 + yy) * 16 + xx];
    float n2 = val * val;
    #pragma unroll
    for (int s = 16; s > 0; s >>= 1) n2 += __shfl_xor_sync(0xffffffffu, n2, s);
    float scale = (n2 / (1.0f + n2)) * rsqrtf(n2 + CAP_EPS);
    g_u[(b * 1024 + p) * 32 + lane] = val * scale;
}

// ---------------- K5: u_hat[b,p,t,o] = sum_i u[b,p,i] * Wr[p,t,o,i] --------
__global__ __launch_bounds__(160) void k5_uhat(const float* __restrict__ Wr) {
    int p = blockIdx.x;
    __shared__ float wt[5120];
    __shared__ float us[32];
    for (int j = threadIdx.x; j < 5120; j += 160) {
        float v = Wr[p * 5120 + j];
        wt[(j & 31) * 160 + (j >> 5)] = v;
    }
    int tid = threadIdx.x;
    for (int b = 0; b < 64; ++b) {
        __syncthreads();
        if (tid < 32) us[tid] = g_u[(b * 1024 + p) * 32 + tid];
        __syncthreads();
        float acc = 0.0f;
        #pragma unroll
        for (int i = 0; i < 32; ++i)
            acc = fmaf(us[i], wt[i * 160 + tid], acc);
        g_uhat[(b * 1024 + p) * 160 + tid] = acc;
    }
}

// ---------------- K6: dynamic routing (3 iters) + likelihood ---------------
__global__ __launch_bounds__(160) void k6_routing(float* __restrict__ out) {
    __shared__ float blog[10240];
    __shared__ float ctile[640];
    __shared__ float sv[160];
    __shared__ float vv[160];

    int b   = blockIdx.x;
    int tid = threadIdx.x;
    int t   = tid >> 4;
    int o   = tid & 15;

    for (int i = tid; i < 10240; i += 160) blog[i] = 0.0f;
    __syncthreads();

    const float* uh = g_uhat + b * (1024 * 160);

    for (int iter = 0; iter < 3; ++iter) {
        float s = 0.0f;
        for (int p0 = 0; p0 < 1024; p0 += 64) {
            if (tid < 64) {
                int p = p0 + tid;
                float bl[10];
                float mx = -1e30f;
                #pragma unroll
                for (int k = 0; k < 10; ++k) { bl[k] = blog[p * 10 + k]; mx = fmaxf(mx, bl[k]); }
                float z = 0.0f;
                #pragma unroll
                for (int k = 0; k < 10; ++k) { bl[k] = expf(bl[k] - mx); z += bl[k]; }
                float inv = 1.0f / z;
                #pragma unroll
                for (int k = 0; k < 10; ++k) ctile[tid * 10 + k] = bl[k] * inv;
            }
            __syncthreads();
            #pragma unroll 4
            for (int pp = 0; pp < 64; ++pp)
                s = fmaf(ctile[pp * 10 + t], uh[(p0 + pp) * 160 + tid], s);
            __syncthreads();
        }
        sv[tid] = s;
        __syncthreads();

        float n2 = 0.0f;
        #pragma unroll
        for (int k = 0; k < 16; ++k) { float q = sv[t * 16 + k]; n2 = fmaf(q, q, n2); }
        float vval = s * (n2 / (1.0f + n2)) * rsqrtf(n2 + CAP_EPS);
        vv[tid] = vval;
        __syncthreads();

        if (iter < 2) {
            int tt = tid % 10;
            int pg = tid / 10;
            float4 v0 = *(float4*)&vv[tt * 16 + 0];
            float4 v1 = *(float4*)&vv[tt * 16 + 4];
            float4 v2 = *(float4*)&vv[tt * 16 + 8];
            float4 v3 = *(float4*)&vv[tt * 16 + 12];
            for (int k = 0; k < 64; ++k) {
                int p = pg * 64 + k;
                const float4* u4 = (const float4*)(uh + p * 160 + tt * 16);
                float4 a = u4[0], bb = u4[1], cc = u4[2], dd = u4[3];
                float d = a.x * v0.x + a.y * v0.y + a.z * v0.z + a.w * v0.w
                        + bb.x * v1.x + bb.y * v1.y + bb.z * v1.z + bb.w * v1.w
                        + cc.x * v2.x + cc.y * v2.y + cc.z * v2.z + cc.w * v2.w
                        + dd.x * v3.x + dd.y * v3.y + dd.z * v3.z + dd.w * v3.w;
                blog[p * 10 + tt] += d;
            }
            __syncthreads();
        }
    }

    if (o == 0) {
        float n2 = 0.0f;
        #pragma unroll
        for (int k = 0; k < 16; ++k) { float q = vv[t * 16 + k]; n2 = fmaf(q, q, n2); }
        out[b * 10 + t] = sqrtf(n2 + CAP_EPS);
    }
}

// ---------------- launch ---------------------------------------------------
extern "C" void kernel_launch(void* const* d_in, const int* in_sizes, int n_in,
                              void* d_out, int out_size) {
    const float* x  = (const float*)d_in[0];
    const float* w1 = (const float*)d_in[1];
    const float* b1 = (const float*)d_in[2];
    const float* w2 = (const float*)d_in[3];
    const float* b2 = (const float*)d_in[4];
    const float* wc = (const float*)d_in[5];
    const float* bc = (const float*)d_in[6];
    const float* Wr = (const float*)d_in[7];
    float* out = (float*)d_out;

    static int attr_done = 0;
    if (!attr_done) {
        cudaFuncSetAttribute(k2_conv2_mma,
                             cudaFuncAttributeMaxDynamicSharedMemorySize, K2_SMEM);
        attr_done = 1;
    }

    k2w_pack<<<400, 256>>>(w2);
    k1_conv1_pool<<<dim3(6, 16, 64), dim3(14, 8)>>>(x, w1, b1);
    k2_conv2_mma<<<dim3(12, 64), 256, K2_SMEM>>>(b2);
    k3_conv3<<<dim3(8, 64), 128>>>(wc, bc);
    k4_squash_u<<<8192, 256>>>();
    k5_uhat<<<1024, 160>>>(Wr);
    k6_routing<<<64, 160>>>(out);
}